// round 8
// baseline (speedup 1.0000x reference)
#include <cuda_runtime.h>
#include <cstdint>

#define N_NODES 50000
#define N_EDGES 800000
#define N_GRAPHS 2048
#define IN_DIM 128
#define HID 256
#define N_LAYERS 4
#define BN_EPS 1e-5f

// ---------------- scratch (no allocations allowed) ----------------
__device__ __align__(16) float g_dinv[N_NODES];
__device__ __align__(16) float g_self[N_NODES];
__device__ __align__(16) float g_H[(size_t)N_NODES * HID];   // h = X @ W
__device__ __align__(16) float g_X[(size_t)N_NODES * HID];   // activations
__device__ __align__(16) float g_sc4[N_LAYERS][HID];
__device__ __align__(16) float g_sh4[N_LAYERS][HID];
__device__ int   g_degi[N_NODES];
__device__ int   g_fill[N_NODES];
__device__ int   g_off[N_NODES + 1];
__device__ int   g_csr_src[N_EDGES];
__device__ __align__(16) float g_csr_w[N_EDGES];
__device__ int   g_start[N_GRAPHS + 1];
__device__ int   g_is64;

// ---------------- index dtype sniffing ----------------
__global__ void k_sniff(const unsigned* __restrict__ ei_raw) {
    unsigned acc = 0;
    for (int i = 1; i < 128; i += 2) acc |= ei_raw[i];
    g_is64 = (acc == 0) ? 1 : 0;
}

__device__ __forceinline__ int idx_at(const void* base, long long i) {
    if (g_is64) return (int)((const long long*)base)[i];
    return ((const int*)base)[i];
}

// ---------------- setup: degree / norms / CSR / bounds / BN prep -------
__global__ void k_zero_int() {
    int i = blockIdx.x * blockDim.x + threadIdx.x;
    if (i < N_NODES) { g_degi[i] = 0; g_fill[i] = 0; }
}

__global__ void k_degi(const void* __restrict__ ei) {
    int e = blockIdx.x * blockDim.x + threadIdx.x;
    if (e < N_EDGES) atomicAdd(&g_degi[idx_at(ei, (long long)N_EDGES + e)], 1);
}

__global__ void k_norms() {
    int i = blockIdx.x * blockDim.x + threadIdx.x;
    if (i < N_NODES) {
        float d = (float)g_degi[i] + 1.0f;   // self loop
        g_dinv[i] = rsqrtf(d);
        g_self[i] = 1.0f / d;
    }
}

__global__ __launch_bounds__(1024)
void k_scan() {
    const int C = (N_NODES + 1023) / 1024;   // 49
    __shared__ int ps[1024];
    int t = threadIdx.x;
    int base = t * C;
    int sum = 0;
    for (int c = 0; c < C; c++) {
        int i = base + c;
        if (i < N_NODES) sum += g_degi[i];
    }
    ps[t] = sum;
    __syncthreads();
    for (int off = 1; off < 1024; off <<= 1) {
        int v = (t >= off) ? ps[t - off] : 0;
        __syncthreads();
        ps[t] += v;
        __syncthreads();
    }
    int ex = (t == 0) ? 0 : ps[t - 1];
    for (int c = 0; c < C; c++) {
        int i = base + c;
        if (i < N_NODES) { g_off[i] = ex; ex += g_degi[i]; }
    }
    if (t == 1023) g_off[N_NODES] = ex;
}

__global__ void k_fill(const void* __restrict__ ei) {
    int e = blockIdx.x * blockDim.x + threadIdx.x;
    if (e >= N_EDGES) return;
    int s = idx_at(ei, e);
    int d = idx_at(ei, (long long)N_EDGES + e);
    int pos = g_off[d] + atomicAdd(&g_fill[d], 1);
    g_csr_src[pos] = s;
    g_csr_w[pos] = g_dinv[s] * g_dinv[d];
}

__global__ void k_gbounds(const void* __restrict__ batch) {
    int i = blockIdx.x * blockDim.x + threadIdx.x;
    if (i > N_NODES) return;
    if (i == 0) {
        int b0 = idx_at(batch, 0);
        for (int g = 0; g <= b0; g++) g_start[g] = 0;
    } else if (i == N_NODES) {
        int bl = idx_at(batch, N_NODES - 1);
        for (int g = bl + 1; g <= N_GRAPHS; g++) g_start[g] = N_NODES;
    } else {
        int bp = idx_at(batch, i - 1), bc = idx_at(batch, i);
        for (int g = bp + 1; g <= bc; g++) g_start[g] = i;
    }
}

__global__ void k_prep(const float* __restrict__ convB,
                       const float* __restrict__ gamma,
                       const float* __restrict__ beta,
                       const float* __restrict__ mean,
                       const float* __restrict__ var) {
    int j = threadIdx.x;   // 256
    for (int l = 0; l < N_LAYERS; l++) {
        int o = l * HID + j;
        float sc = gamma[o] * rsqrtf(var[o] + BN_EPS);
        g_sc4[l][j] = sc;
        g_sh4[l][j] = sc * (convB[o] - mean[o]) + beta[o];
    }
}

// ---------------- tf32 split helpers ----------------
__device__ __forceinline__ void split_tf32(float x, unsigned& hi, unsigned& lo) {
    unsigned h;
    asm("cvt.rna.tf32.f32 %0, %1;" : "=r"(h) : "f"(x));
    float rem = x - __uint_as_float(h);
    unsigned l;
    asm("cvt.rna.tf32.f32 %0, %1;" : "=r"(l) : "f"(rem));
    hi = h; lo = l;
}

__device__ __forceinline__ void mma_tf32(float* d, const unsigned* a, const unsigned* b) {
    asm volatile(
        "mma.sync.aligned.m16n8k8.row.col.f32.tf32.tf32.f32 "
        "{%0,%1,%2,%3}, {%4,%5,%6,%7}, {%8,%9}, {%0,%1,%2,%3};"
        : "+f"(d[0]), "+f"(d[1]), "+f"(d[2]), "+f"(d[3])
        : "r"(a[0]), "r"(a[1]), "r"(a[2]), "r"(a[3]), "r"(b[0]), "r"(b[1]));
}

// ---------------- tensor-core GEMM: g_H = A[N,K] @ W[K,256] ------------
// Block tile 128x128, K stages of 16. 8 warps; each warp 64x32 via 4x4
// m16n8k8 tiles. Operands split to tf32 hi/lo; acc = hi*hi + hi*lo + lo*hi.
#define APAD 136
template<int K, bool USE_GX>
__global__ __launch_bounds__(256, 1)
void k_gemm_tc(const float* __restrict__ Ain, const float* __restrict__ W) {
    __shared__ unsigned Ahi[16][APAD];
    __shared__ unsigned Alo[16][APAD];
    __shared__ unsigned Bhi[16][APAD];
    __shared__ unsigned Blo[16][APAD];

    const float* A = USE_GX ? (const float*)g_X : Ain;
    int t = threadIdx.x;
    int lane = t & 31;
    int tig = lane & 3;        // thread-in-group (k / col pair)
    int grp = lane >> 2;       // group id (row / col)
    int warpId = t >> 5;
    int wm = (warpId & 1) * 64;
    int wn = (warpId >> 1) * 32;
    int rowBase = blockIdx.x * 128;
    int colBase = blockIdx.y * 128;

    // load-phase mapping
    int lr   = t >> 1;         // A row within tile (0..127)
    int lhalf = (t & 1) * 8;   // k-offset 0 or 8
    int bk2  = t >> 4;         // B k-row (0..15)
    int n8   = (t & 15) * 8;   // B col offset

    float acc[4][4][4] = {};

    for (int k0 = 0; k0 < K; k0 += 16) {
        // ---- stage load + split ----
        {
            int row = rowBase + lr;
            float4 v0 = make_float4(0.f, 0.f, 0.f, 0.f), v1 = v0;
            if (row < N_NODES) {
                const float* ap = A + (size_t)row * K + k0 + lhalf;
                v0 = *(const float4*)(ap);
                v1 = *(const float4*)(ap + 4);
            }
            float av[8] = {v0.x, v0.y, v0.z, v0.w, v1.x, v1.y, v1.z, v1.w};
            #pragma unroll
            for (int q = 0; q < 8; q++) {
                unsigned h, l; split_tf32(av[q], h, l);
                Ahi[lhalf + q][lr] = h;
                Alo[lhalf + q][lr] = l;
            }
            const float* wp = W + (size_t)(k0 + bk2) * HID + colBase + n8;
            float4 w0 = *(const float4*)(wp);
            float4 w1 = *(const float4*)(wp + 4);
            float bv[8] = {w0.x, w0.y, w0.z, w0.w, w1.x, w1.y, w1.z, w1.w};
            #pragma unroll
            for (int q = 0; q < 8; q++) {
                unsigned h, l; split_tf32(bv[q], h, l);
                Bhi[bk2][n8 + q] = h;
                Blo[bk2][n8 + q] = l;
            }
        }
        __syncthreads();

        // ---- compute: two k8 steps ----
        #pragma unroll
        for (int ks = 0; ks < 16; ks += 8) {
            unsigned bh[4][2], bl[4][2];
            #pragma unroll
            for (int nt = 0; nt < 4; nt++) {
                int n = wn + nt * 8 + grp;
                bh[nt][0] = Bhi[ks + tig][n];
                bh[nt][1] = Bhi[ks + tig + 4][n];
                bl[nt][0] = Blo[ks + tig][n];
                bl[nt][1] = Blo[ks + tig + 4][n];
            }
            #pragma unroll
            for (int mt = 0; mt < 4; mt++) {
                int m = wm + mt * 16 + grp;
                unsigned ah[4] = {Ahi[ks + tig][m],     Ahi[ks + tig][m + 8],
                                  Ahi[ks + tig + 4][m], Ahi[ks + tig + 4][m + 8]};
                unsigned al[4] = {Alo[ks + tig][m],     Alo[ks + tig][m + 8],
                                  Alo[ks + tig + 4][m], Alo[ks + tig + 4][m + 8]};
                #pragma unroll
                for (int nt = 0; nt < 4; nt++) {
                    mma_tf32(acc[mt][nt], ah, bh[nt]);
                    mma_tf32(acc[mt][nt], ah, bl[nt]);
                    mma_tf32(acc[mt][nt], al, bh[nt]);
                }
            }
        }
        __syncthreads();
    }

    // ---- epilogue ----
    #pragma unroll
    for (int mt = 0; mt < 4; mt++) {
        int r0 = rowBase + wm + mt * 16 + grp;
        int r1 = r0 + 8;
        #pragma unroll
        for (int nt = 0; nt < 4; nt++) {
            int c = colBase + wn + nt * 8 + 2 * tig;
            if (r0 < N_NODES)
                *(float2*)(g_H + (size_t)r0 * HID + c) = make_float2(acc[mt][nt][0], acc[mt][nt][1]);
            if (r1 < N_NODES)
                *(float2*)(g_H + (size_t)r1 * HID + c) = make_float2(acc[mt][nt][2], acc[mt][nt][3]);
        }
    }
}

// ---------------- fused gather + self + BN + ReLU ----------------
__global__ __launch_bounds__(256)
void k_agg(int layer) {
    int tid = blockIdx.x * blockDim.x + threadIdx.x;
    int i = tid >> 6;
    if (i >= N_NODES) return;
    int j = (tid & 63) << 2;

    float s = g_self[i];
    float4 h = *(const float4*)(g_H + (size_t)i * HID + j);
    float4 acc = make_float4(h.x * s, h.y * s, h.z * s, h.w * s);

    int k = g_off[i], kend = g_off[i + 1];
    for (; k + 1 < kend; k += 2) {
        int   s0 = g_csr_src[k],     s1 = g_csr_src[k + 1];
        float w0 = g_csr_w[k],       w1 = g_csr_w[k + 1];
        float4 h0 = *(const float4*)(g_H + (size_t)s0 * HID + j);
        float4 h1 = *(const float4*)(g_H + (size_t)s1 * HID + j);
        acc.x += w0 * h0.x + w1 * h1.x;
        acc.y += w0 * h0.y + w1 * h1.y;
        acc.z += w0 * h0.z + w1 * h1.z;
        acc.w += w0 * h0.w + w1 * h1.w;
    }
    if (k < kend) {
        int   s0 = g_csr_src[k];
        float w0 = g_csr_w[k];
        float4 h0 = *(const float4*)(g_H + (size_t)s0 * HID + j);
        acc.x += w0 * h0.x; acc.y += w0 * h0.y;
        acc.z += w0 * h0.z; acc.w += w0 * h0.w;
    }

    float4 sc = *(const float4*)(&g_sc4[layer][j]);
    float4 sh = *(const float4*)(&g_sh4[layer][j]);
    float4 o;
    o.x = fmaxf(acc.x * sc.x + sh.x, 0.f);
    o.y = fmaxf(acc.y * sc.y + sh.y, 0.f);
    o.z = fmaxf(acc.z * sc.z + sh.z, 0.f);
    o.w = fmaxf(acc.w * sc.w + sh.w, 0.f);
    *(float4*)(g_X + (size_t)i * HID + j) = o;
}

// ---------------- fused mean-pool + MLP head ----------------
__global__ __launch_bounds__(128)
void k_pmlp(const float* __restrict__ lin1W, const float* __restrict__ lin1b,
            const float* __restrict__ lin2W, const float* __restrict__ lin2b,
            float* __restrict__ out) {
    __shared__ float row[HID];
    __shared__ float red4[4];
    int g = blockIdx.x;
    int t = threadIdx.x;   // 128

    int s = g_start[g], e = g_start[g + 1];
    float r0 = 0.f, r1 = 0.f;
    for (int n = s; n < e; n++) {
        r0 += g_X[(size_t)n * HID + t];
        r1 += g_X[(size_t)n * HID + t + 128];
    }
    float inv = 1.0f / fmaxf((float)(e - s), 1.0f);
    row[t] = r0 * inv;
    row[t + 128] = r1 * inv;
    __syncthreads();

    float acc = lin1b[t];
    #pragma unroll 8
    for (int k = 0; k < HID; k++)
        acc += row[k] * lin1W[(size_t)k * 128 + t];
    float h = fmaxf(acc, 0.f);

    float p = h * lin2W[t];
    #pragma unroll
    for (int o = 16; o > 0; o >>= 1)
        p += __shfl_down_sync(0xffffffffu, p, o);
    if ((t & 31) == 0) red4[t >> 5] = p;
    __syncthreads();
    if (t == 0) out[g] = red4[0] + red4[1] + red4[2] + red4[3] + lin2b[0];
}

// ---------------- launch ----------------
extern "C" void kernel_launch(void* const* d_in, const int* in_sizes, int n_in,
                              void* d_out, int out_size) {
    const float* x      = (const float*)d_in[0];
    const void*  ei     = d_in[1];
    const void*  batch  = d_in[2];
    const float* convW0 = (const float*)d_in[3];
    const float* convWs = (const float*)d_in[4];
    const float* convB  = (const float*)d_in[5];
    const float* bn_g   = (const float*)d_in[6];
    const float* bn_b   = (const float*)d_in[7];
    const float* bn_m   = (const float*)d_in[8];
    const float* bn_v   = (const float*)d_in[9];
    const float* lin1W  = (const float*)d_in[10];
    const float* lin1b  = (const float*)d_in[11];
    const float* lin2W  = (const float*)d_in[12];
    const float* lin2b  = (const float*)d_in[13];
    float* out = (float*)d_out;

    const int TPB = 256;
    int nodeBlocks = (N_NODES + TPB - 1) / TPB;
    int nb1Blocks  = (N_NODES + 1 + TPB - 1) / TPB;
    int edgeBlocks = (N_EDGES + TPB - 1) / TPB;
    int aggBlocks  = (N_NODES * 64 + TPB - 1) / TPB;   // 12500

    k_sniff<<<1, 1>>>((const unsigned*)ei);
    k_zero_int<<<nodeBlocks, TPB>>>();
    k_degi<<<edgeBlocks, TPB>>>(ei);
    k_norms<<<nodeBlocks, TPB>>>();
    k_scan<<<1, 1024>>>();
    k_fill<<<edgeBlocks, TPB>>>(ei);
    k_gbounds<<<nb1Blocks, TPB>>>(batch);
    k_prep<<<1, HID>>>(convB, bn_g, bn_b, bn_m, bn_v);

    dim3 ggrid((N_NODES + 127) / 128, HID / 128);
    for (int l = 0; l < N_LAYERS; l++) {
        if (l == 0) {
            k_gemm_tc<IN_DIM, false><<<ggrid, 256>>>(x, convW0);
        } else {
            const float* W = convWs + (size_t)(l - 1) * HID * HID;
            k_gemm_tc<HID, true><<<ggrid, 256>>>(nullptr, W);
        }
        k_agg<<<aggBlocks, TPB>>>(l);
    }

    k_pmlp<<<N_GRAPHS, 128>>>(lin1W, lin1b, lin2W, lin2b, out);
}

// round 14
// speedup vs baseline: 1.1852x; 1.1852x over previous
#include <cuda_runtime.h>
#include <cstdint>

#define N_NODES 50000
#define N_EDGES 800000
#define N_GRAPHS 2048
#define IN_DIM 128
#define HID 256
#define N_LAYERS 4
#define BN_EPS 1e-5f

// ---------------- scratch (no allocations allowed) ----------------
__device__ __align__(16) float g_dinv[N_NODES];
__device__ __align__(16) float g_self[N_NODES];
__device__ __align__(16) float g_H[(size_t)N_NODES * HID];   // h = X @ W
__device__ __align__(16) float g_X[(size_t)N_NODES * HID];   // activations
__device__ __align__(16) float g_sc4[N_LAYERS][HID];
__device__ __align__(16) float g_sh4[N_LAYERS][HID];
__device__ int   g_degi[N_NODES];
__device__ int   g_fill[N_NODES];
__device__ int   g_off[N_NODES + 1];
__device__ int   g_csr_src[N_EDGES];
__device__ __align__(16) float g_csr_w[N_EDGES];
__device__ int   g_start[N_GRAPHS + 1];
__device__ int   g_is64;

// ---------------- index dtype sniffing ----------------
__global__ void k_sniff(const unsigned* __restrict__ ei_raw) {
    unsigned acc = 0;
    for (int i = 1; i < 128; i += 2) acc |= ei_raw[i];
    g_is64 = (acc == 0) ? 1 : 0;
}

__device__ __forceinline__ int idx_at(const void* base, long long i) {
    if (g_is64) return (int)((const long long*)base)[i];
    return ((const int*)base)[i];
}

// ---------------- setup kernels ----------------
__global__ void k_zero_int() {
    int i = blockIdx.x * blockDim.x + threadIdx.x;
    if (i < N_NODES) { g_degi[i] = 0; g_fill[i] = 0; }
}

__global__ void k_degi(const void* __restrict__ ei) {
    int e = blockIdx.x * blockDim.x + threadIdx.x;
    if (e < N_EDGES) atomicAdd(&g_degi[idx_at(ei, (long long)N_EDGES + e)], 1);
}

__global__ void k_norms() {
    int i = blockIdx.x * blockDim.x + threadIdx.x;
    if (i < N_NODES) {
        float d = (float)g_degi[i] + 1.0f;   // self loop
        g_dinv[i] = rsqrtf(d);
        g_self[i] = 1.0f / d;
    }
}

__global__ __launch_bounds__(1024)
void k_scan() {
    const int C = (N_NODES + 1023) / 1024;   // 49
    __shared__ int ps[1024];
    int t = threadIdx.x;
    int base = t * C;
    int sum = 0;
    for (int c = 0; c < C; c++) {
        int i = base + c;
        if (i < N_NODES) sum += g_degi[i];
    }
    ps[t] = sum;
    __syncthreads();
    for (int off = 1; off < 1024; off <<= 1) {
        int v = (t >= off) ? ps[t - off] : 0;
        __syncthreads();
        ps[t] += v;
        __syncthreads();
    }
    int ex = (t == 0) ? 0 : ps[t - 1];
    for (int c = 0; c < C; c++) {
        int i = base + c;
        if (i < N_NODES) { g_off[i] = ex; ex += g_degi[i]; }
    }
    if (t == 1023) g_off[N_NODES] = ex;
}

__global__ void k_fill(const void* __restrict__ ei) {
    int e = blockIdx.x * blockDim.x + threadIdx.x;
    if (e >= N_EDGES) return;
    int s = idx_at(ei, e);
    int d = idx_at(ei, (long long)N_EDGES + e);
    int pos = g_off[d] + atomicAdd(&g_fill[d], 1);
    g_csr_src[pos] = s;
    g_csr_w[pos] = g_dinv[s] * g_dinv[d];
}

__global__ void k_gbounds(const void* __restrict__ batch) {
    int i = blockIdx.x * blockDim.x + threadIdx.x;
    if (i > N_NODES) return;
    if (i == 0) {
        int b0 = idx_at(batch, 0);
        for (int g = 0; g <= b0; g++) g_start[g] = 0;
    } else if (i == N_NODES) {
        int bl = idx_at(batch, N_NODES - 1);
        for (int g = bl + 1; g <= N_GRAPHS; g++) g_start[g] = N_NODES;
    } else {
        int bp = idx_at(batch, i - 1), bc = idx_at(batch, i);
        for (int g = bp + 1; g <= bc; g++) g_start[g] = i;
    }
}

__global__ void k_prep(const float* __restrict__ convB,
                       const float* __restrict__ gamma,
                       const float* __restrict__ beta,
                       const float* __restrict__ mean,
                       const float* __restrict__ var) {
    int j = threadIdx.x;   // 256
    for (int l = 0; l < N_LAYERS; l++) {
        int o = l * HID + j;
        float sc = gamma[o] * rsqrtf(var[o] + BN_EPS);
        g_sc4[l][j] = sc;
        g_sh4[l][j] = sc * (convB[o] - mean[o]) + beta[o];
    }
}

// ---------------- helpers ----------------
__device__ __forceinline__ uint32_t smem_u32(const void* p) {
    uint32_t a;
    asm("{ .reg .u64 t; cvta.to.shared.u64 t, %1; cvt.u32.u64 %0, t; }"
        : "=r"(a) : "l"(p));
    return a;
}

// ---------------- FFMA2 GEMM: g_H = A[N,K] @ W[K,256] ----------------
// Block tile 128x128, BK=8, 128 threads, 16x8 per thread.
// Accumulators are f32x2 pairs along M (rows r, r+1); b values duplicated
// into both halves; fma.rn.f32x2 -> SASS FFMA2 (2 fp32 FMA / fma-slot).
#define BM 128
#define BN 128
#define BK 8

template<int K, bool USE_GX>
__global__ __launch_bounds__(128)
void k_gemm2(const float* __restrict__ Ain, const float* __restrict__ W) {
    __shared__ float As[BK][BM + 4];
    __shared__ float Bs[BK][BN + 4];

    const float* A = USE_GX ? (const float*)g_X : Ain;
    int t = threadIdx.x;
    int tx = t & 15;        // col group: cols tx*8 .. +7
    int ty = t >> 4;        // row group: rows ty*16 .. +15
    int rowBase = blockIdx.x * BM;
    int colBase = blockIdx.y * BN;

    int bk = t >> 4;        // B stage k-row (0..7)
    int bc = (t & 15) * 8;  // B stage col

    unsigned long long acc[8][8];
    #pragma unroll
    for (int i = 0; i < 8; i++)
        #pragma unroll
        for (int j = 0; j < 8; j++) acc[i][j] = 0ull;

    uint32_t asB = smem_u32(As);

    float4 aP0, aP1, bP0, bP1;
    {
        int row = rowBase + t;
        if (row < N_NODES) {
            aP0 = *(const float4*)(A + (size_t)row * K + 0);
            aP1 = *(const float4*)(A + (size_t)row * K + 4);
        } else { aP0 = aP1 = make_float4(0.f, 0.f, 0.f, 0.f); }
        const float* wp = W + (size_t)bk * HID + colBase + bc;
        bP0 = *(const float4*)wp;
        bP1 = *(const float4*)(wp + 4);
    }

    for (int k0 = 0; k0 < K; k0 += BK) {
        As[0][t] = aP0.x; As[1][t] = aP0.y; As[2][t] = aP0.z; As[3][t] = aP0.w;
        As[4][t] = aP1.x; As[5][t] = aP1.y; As[6][t] = aP1.z; As[7][t] = aP1.w;
        *(float4*)&Bs[bk][bc]     = bP0;
        *(float4*)&Bs[bk][bc + 4] = bP1;
        __syncthreads();

        if (k0 + BK < K) {
            int row = rowBase + t;
            if (row < N_NODES) {
                aP0 = *(const float4*)(A + (size_t)row * K + k0 + 8);
                aP1 = *(const float4*)(A + (size_t)row * K + k0 + 12);
            } else { aP0 = aP1 = make_float4(0.f, 0.f, 0.f, 0.f); }
            const float* wp = W + (size_t)(k0 + 8 + bk) * HID + colBase + bc;
            bP0 = *(const float4*)wp;
            bP1 = *(const float4*)(wp + 4);
        }

        #pragma unroll
        for (int k = 0; k < BK; k++) {
            unsigned long long ap[8];
            uint32_t ab = asB + (uint32_t)(k * (BM + 4) + ty * 16) * 4u;
            asm("ld.shared.v2.b64 {%0,%1}, [%2];" : "=l"(ap[0]), "=l"(ap[1]) : "r"(ab));
            asm("ld.shared.v2.b64 {%0,%1}, [%2];" : "=l"(ap[2]), "=l"(ap[3]) : "r"(ab + 16));
            asm("ld.shared.v2.b64 {%0,%1}, [%2];" : "=l"(ap[4]), "=l"(ap[5]) : "r"(ab + 32));
            asm("ld.shared.v2.b64 {%0,%1}, [%2];" : "=l"(ap[6]), "=l"(ap[7]) : "r"(ab + 48));

            float4 b0 = *(const float4*)&Bs[k][tx * 8];
            float4 b1 = *(const float4*)&Bs[k][tx * 8 + 4];
            float bv[8] = {b0.x, b0.y, b0.z, b0.w, b1.x, b1.y, b1.z, b1.w};
            unsigned long long bd[8];
            #pragma unroll
            for (int j = 0; j < 8; j++)
                asm("mov.b64 %0, {%1, %1};" : "=l"(bd[j]) : "f"(bv[j]));

            #pragma unroll
            for (int i = 0; i < 8; i++)
                #pragma unroll
                for (int j = 0; j < 8; j++)
                    asm("fma.rn.f32x2 %0, %1, %2, %0;"
                        : "+l"(acc[i][j]) : "l"(ap[i]), "l"(bd[j]));
        }
        __syncthreads();
    }

    // epilogue: pair i covers rows (ty*16 + 2i, +1)
    #pragma unroll
    for (int i = 0; i < 8; i++) {
        int r0 = rowBase + ty * 16 + i * 2;
        float lo[8], hi[8];
        #pragma unroll
        for (int j = 0; j < 8; j++)
            asm("mov.b64 {%0, %1}, %2;" : "=f"(lo[j]), "=f"(hi[j]) : "l"(acc[i][j]));
        if (r0 < N_NODES) {
            float* p = g_H + (size_t)r0 * HID + colBase + tx * 8;
            *(float4*)p       = make_float4(lo[0], lo[1], lo[2], lo[3]);
            *(float4*)(p + 4) = make_float4(lo[4], lo[5], lo[6], lo[7]);
        }
        if (r0 + 1 < N_NODES) {
            float* p = g_H + (size_t)(r0 + 1) * HID + colBase + tx * 8;
            *(float4*)p       = make_float4(hi[0], hi[1], hi[2], hi[3]);
            *(float4*)(p + 4) = make_float4(hi[4], hi[5], hi[6], hi[7]);
        }
    }
}

// ---------------- fused gather + self + BN + ReLU ----------------
__global__ __launch_bounds__(256)
void k_agg(int layer) {
    int tid = blockIdx.x * blockDim.x + threadIdx.x;
    int i = tid >> 6;
    if (i >= N_NODES) return;
    int j = (tid & 63) << 2;

    float s = g_self[i];
    float4 h = *(const float4*)(g_H + (size_t)i * HID + j);
    float4 acc = make_float4(h.x * s, h.y * s, h.z * s, h.w * s);

    int k = g_off[i], kend = g_off[i + 1];
    for (; k + 1 < kend; k += 2) {
        int   s0 = g_csr_src[k],     s1 = g_csr_src[k + 1];
        float w0 = g_csr_w[k],       w1 = g_csr_w[k + 1];
        float4 h0 = *(const float4*)(g_H + (size_t)s0 * HID + j);
        float4 h1 = *(const float4*)(g_H + (size_t)s1 * HID + j);
        acc.x += w0 * h0.x + w1 * h1.x;
        acc.y += w0 * h0.y + w1 * h1.y;
        acc.z += w0 * h0.z + w1 * h1.z;
        acc.w += w0 * h0.w + w1 * h1.w;
    }
    if (k < kend) {
        int   s0 = g_csr_src[k];
        float w0 = g_csr_w[k];
        float4 h0 = *(const float4*)(g_H + (size_t)s0 * HID + j);
        acc.x += w0 * h0.x; acc.y += w0 * h0.y;
        acc.z += w0 * h0.z; acc.w += w0 * h0.w;
    }

    float4 sc = *(const float4*)(&g_sc4[layer][j]);
    float4 sh = *(const float4*)(&g_sh4[layer][j]);
    float4 o;
    o.x = fmaxf(acc.x * sc.x + sh.x, 0.f);
    o.y = fmaxf(acc.y * sc.y + sh.y, 0.f);
    o.z = fmaxf(acc.z * sc.z + sh.z, 0.f);
    o.w = fmaxf(acc.w * sc.w + sh.w, 0.f);
    *(float4*)(g_X + (size_t)i * HID + j) = o;
}

// ---------------- fused mean-pool + MLP head ----------------
__global__ __launch_bounds__(128)
void k_pmlp(const float* __restrict__ lin1W, const float* __restrict__ lin1b,
            const float* __restrict__ lin2W, const float* __restrict__ lin2b,
            float* __restrict__ out) {
    __shared__ float row[HID];
    __shared__ float red4[4];
    int g = blockIdx.x;
    int t = threadIdx.x;   // 128

    int s = g_start[g], e = g_start[g + 1];
    float r0 = 0.f, r1 = 0.f;
    for (int n = s; n < e; n++) {
        r0 += g_X[(size_t)n * HID + t];
        r1 += g_X[(size_t)n * HID + t + 128];
    }
    float inv = 1.0f / fmaxf((float)(e - s), 1.0f);
    row[t] = r0 * inv;
    row[t + 128] = r1 * inv;
    __syncthreads();

    float acc = lin1b[t];
    #pragma unroll 8
    for (int k = 0; k < HID; k++)
        acc += row[k] * lin1W[(size_t)k * 128 + t];
    float h = fmaxf(acc, 0.f);

    float p = h * lin2W[t];
    #pragma unroll
    for (int o = 16; o > 0; o >>= 1)
        p += __shfl_down_sync(0xffffffffu, p, o);
    if ((t & 31) == 0) red4[t >> 5] = p;
    __syncthreads();
    if (t == 0) out[g] = red4[0] + red4[1] + red4[2] + red4[3] + lin2b[0];
}

// ---------------- launch ----------------
extern "C" void kernel_launch(void* const* d_in, const int* in_sizes, int n_in,
                              void* d_out, int out_size) {
    const float* x      = (const float*)d_in[0];
    const void*  ei     = d_in[1];
    const void*  batch  = d_in[2];
    const float* convW0 = (const float*)d_in[3];
    const float* convWs = (const float*)d_in[4];
    const float* convB  = (const float*)d_in[5];
    const float* bn_g   = (const float*)d_in[6];
    const float* bn_b   = (const float*)d_in[7];
    const float* bn_m   = (const float*)d_in[8];
    const float* bn_v   = (const float*)d_in[9];
    const float* lin1W  = (const float*)d_in[10];
    const float* lin1b  = (const float*)d_in[11];
    const float* lin2W  = (const float*)d_in[12];
    const float* lin2b  = (const float*)d_in[13];
    float* out = (float*)d_out;

    const int TPB = 256;
    int nodeBlocks = (N_NODES + TPB - 1) / TPB;
    int nb1Blocks  = (N_NODES + 1 + TPB - 1) / TPB;
    int edgeBlocks = (N_EDGES + TPB - 1) / TPB;
    int aggBlocks  = (N_NODES * 64 + TPB - 1) / TPB;   // 12500

    k_sniff<<<1, 1>>>((const unsigned*)ei);
    k_zero_int<<<nodeBlocks, TPB>>>();
    k_degi<<<edgeBlocks, TPB>>>(ei);
    k_norms<<<nodeBlocks, TPB>>>();
    k_scan<<<1, 1024>>>();
    k_fill<<<edgeBlocks, TPB>>>(ei);
    k_gbounds<<<nb1Blocks, TPB>>>(batch);
    k_prep<<<1, HID>>>(convB, bn_g, bn_b, bn_m, bn_v);

    dim3 ggrid((N_NODES + BM - 1) / BM, HID / BN);
    for (int l = 0; l < N_LAYERS; l++) {
        if (l == 0) {
            k_gemm2<IN_DIM, false><<<ggrid, 128>>>(x, convW0);
        } else {
            const float* W = convWs + (size_t)(l - 1) * HID * HID;
            k_gemm2<HID, true><<<ggrid, 128>>>(nullptr, W);
        }
        k_agg<<<aggBlocks, TPB>>>(l);
    }

    k_pmlp<<<N_GRAPHS, 128>>>(lin1W, lin1b, lin2W, lin2b, out);
}